// round 5
// baseline (speedup 1.0000x reference)
#include <cuda_runtime.h>
#include <math.h>

// Problem constants
#define BSZ   4
#define SSZ   2048
#define DM    1024
#define HH    16
#define DHD   64
#define DFF_  4096
#define LNUM  6
#define MS    (BSZ*SSZ)   // 8192 rows

// ---------------------------------------------------------------------------
// Scratch (device globals — no allocation allowed)
// ---------------------------------------------------------------------------
__device__ float g_X[MS*DM];     // running activations
__device__ float g_Q[MS*DM];
__device__ float g_K[MS*DM];
__device__ float g_V[MS*DM];
__device__ float g_T[MS*DM];     // attn output / ffn tmp
__device__ float g_F[(size_t)MS*DFF_];   // ffn hidden
__device__ float g_KV[BSZ*HH*DHD*DHD];
__device__ float g_KS[BSZ*HH*DHD];

// ---------------------------------------------------------------------------
// copy x -> g_X
// ---------------------------------------------------------------------------
__global__ void __launch_bounds__(256) copy_kernel(const float* __restrict__ src,
                                                   float* __restrict__ dst)
{
    size_t i = ((size_t)blockIdx.x * 256 + threadIdx.x) * 4;
    *(float4*)(dst + i) = *(const float4*)(src + i);
}

// ---------------------------------------------------------------------------
// Tiled SGEMM: C[M,N] = act(A[M,K] @ W[K,N] + bias[N])
// ACT: 0 = none, 1 = elu+1 (phi), 2 = relu
// BM=BN=128, BK=16, 256 threads, 8x8 per-thread microtile.
// ---------------------------------------------------------------------------
template<int ACT>
__global__ void __launch_bounds__(256) gemm_kernel(
    const float* __restrict__ A, const float* __restrict__ W,
    const float* __restrict__ bias, float* __restrict__ C,
    int M, int N, int K)
{
    __shared__ float As[16][128];   // A^T tile: As[k][m]
    __shared__ float Bs[16][128];   // Bs[k][n]

    const int tid = threadIdx.x;
    const int bx = blockIdx.x;      // N tile
    const int by = blockIdx.y;      // M tile

    const float* Ab = A + (size_t)by * 128 * K;
    const float* Wb = W + (size_t)bx * 128;

    const int ty = tid >> 4, tx = tid & 15;
    const int row0 = ty * 8, col0 = tx * 8;

    float acc[8][8];
#pragma unroll
    for (int i = 0; i < 8; i++)
#pragma unroll
        for (int j = 0; j < 8; j++) acc[i][j] = 0.f;

    for (int k0 = 0; k0 < K; k0 += 16) {
#pragma unroll
        for (int j = 0; j < 2; j++) {
            int idx = tid + j * 256;          // 0..511
            // A tile: 128 rows x 16 cols  = 512 float4 (4 per row)
            int r  = idx >> 2;
            int c4 = (idx & 3) * 4;
            float4 va = *(const float4*)(Ab + (size_t)r * K + k0 + c4);
            As[c4 + 0][r] = va.x;
            As[c4 + 1][r] = va.y;
            As[c4 + 2][r] = va.z;
            As[c4 + 3][r] = va.w;
            // B tile: 16 rows x 128 cols = 512 float4 (32 per row)
            int kr = idx >> 5;
            int n4 = (idx & 31) * 4;
            float4 vb = *(const float4*)(Wb + (size_t)(k0 + kr) * N + n4);
            *(float4*)&Bs[kr][n4] = vb;
        }
        __syncthreads();

#pragma unroll
        for (int kk = 0; kk < 16; kk++) {
            float a[8], bb[8];
            *(float4*)&a[0]  = *(const float4*)&As[kk][row0];
            *(float4*)&a[4]  = *(const float4*)&As[kk][row0 + 4];
            *(float4*)&bb[0] = *(const float4*)&Bs[kk][col0];
            *(float4*)&bb[4] = *(const float4*)&Bs[kk][col0 + 4];
#pragma unroll
            for (int i = 0; i < 8; i++)
#pragma unroll
                for (int j = 0; j < 8; j++)
                    acc[i][j] = fmaf(a[i], bb[j], acc[i][j]);
        }
        __syncthreads();
    }

    float bj[8];
#pragma unroll
    for (int j = 0; j < 8; j++) bj[j] = bias[bx * 128 + col0 + j];

    float* Cb = C + (size_t)(by * 128) * N + bx * 128;
#pragma unroll
    for (int i = 0; i < 8; i++) {
        float o[8];
#pragma unroll
        for (int j = 0; j < 8; j++) {
            float v = acc[i][j] + bj[j];
            if (ACT == 1) v = (v > 0.f) ? (v + 1.f) : __expf(v);  // elu(v)+1
            if (ACT == 2) v = fmaxf(v, 0.f);
            o[j] = v;
        }
        *(float4*)(Cb + (size_t)(row0 + i) * N + col0)     = *(float4*)&o[0];
        *(float4*)(Cb + (size_t)(row0 + i) * N + col0 + 4) = *(float4*)&o[4];
    }
}

// ---------------------------------------------------------------------------
// kv[b,h,d,m] = sum_s k[b,s,h,d] * v[b,s,h,m];  ksum[b,h,d] = sum_s k[b,s,h,d]
// grid = B*H blocks, 256 threads; each thread owns a 4x4 tile of the 64x64 kv.
// ---------------------------------------------------------------------------
__global__ void __launch_bounds__(256) kv_reduce_kernel(
    const float* __restrict__ Kx, const float* __restrict__ Vx,
    float* __restrict__ KVo, float* __restrict__ KSo)
{
    const int bh = blockIdx.x;
    const int b = bh >> 4, h = bh & 15;
    const float* Kb = Kx + (size_t)b * SSZ * DM + h * DHD;
    const float* Vb = Vx + (size_t)b * SSZ * DM + h * DHD;

    __shared__ float ks[32][64];
    __shared__ float vs[32][64];

    const int tid = threadIdx.x;
    const int ty = tid >> 4, tx = tid & 15;

    float acc[4][4] = {};
    float ksum = 0.f;

    for (int s0 = 0; s0 < SSZ; s0 += 32) {
#pragma unroll
        for (int j = 0; j < 2; j++) {
            int idx = tid + j * 256;
            int r = idx >> 4, c4 = (idx & 15) * 4;
            *(float4*)&ks[r][c4] = *(const float4*)(Kb + (size_t)(s0 + r) * DM + c4);
            *(float4*)&vs[r][c4] = *(const float4*)(Vb + (size_t)(s0 + r) * DM + c4);
        }
        __syncthreads();

#pragma unroll 8
        for (int s = 0; s < 32; s++) {
            float a[4], bv[4];
#pragma unroll
            for (int i = 0; i < 4; i++) a[i] = ks[s][ty * 4 + i];
#pragma unroll
            for (int j = 0; j < 4; j++) bv[j] = vs[s][tx * 4 + j];
#pragma unroll
            for (int i = 0; i < 4; i++)
#pragma unroll
                for (int j = 0; j < 4; j++)
                    acc[i][j] = fmaf(a[i], bv[j], acc[i][j]);
        }
        if (tid < 64) {
#pragma unroll 8
            for (int s = 0; s < 32; s++) ksum += ks[s][tid];
        }
        __syncthreads();
    }

    float* KVb = KVo + (size_t)bh * DHD * DHD;
#pragma unroll
    for (int i = 0; i < 4; i++)
#pragma unroll
        for (int j = 0; j < 4; j++)
            KVb[(ty * 4 + i) * DHD + tx * 4 + j] = acc[i][j];
    if (tid < 64) KSo[bh * DHD + tid] = ksum;
}

// ---------------------------------------------------------------------------
// o[b,s,h,m] = z * sum_d q[b,s,h,d] * kv[b,h,d,m],  z = 1/(q . ksum + 1e-6)
// grid = (B*H, S/64), 256 threads; 64 q-rows per block, 16 out cols per thread.
// ---------------------------------------------------------------------------
__global__ void __launch_bounds__(256) attn_out_kernel(
    const float* __restrict__ Qx, const float* __restrict__ KVi,
    const float* __restrict__ KSi, float* __restrict__ O)
{
    const int bh = blockIdx.x;
    const int b = bh >> 4, h = bh & 15;
    const int s0 = blockIdx.y * 64;

    __shared__ float qs[64][64];
    __shared__ float kvs[64][64];
    __shared__ float kss[64];

    const int tid = threadIdx.x;
    const float* Qb  = Qx + (size_t)(b * SSZ + s0) * DM + h * DHD;
    const float* KVb = KVi + (size_t)bh * DHD * DHD;

#pragma unroll
    for (int j = 0; j < 4; j++) {
        int idx = tid + j * 256;
        int r = idx >> 4, c4 = (idx & 15) * 4;
        *(float4*)&qs[r][c4]  = *(const float4*)(Qb + (size_t)r * DM + c4);
        *(float4*)&kvs[r][c4] = *(const float4*)(KVb + r * DHD + c4);
    }
    if (tid < 64) kss[tid] = KSi[bh * DHD + tid];
    __syncthreads();

    const int row = tid >> 2;
    const int mo  = (tid & 3) * 16;

    float z = 0.f;
#pragma unroll
    for (int d = 0; d < 64; d++) z = fmaf(qs[row][d], kss[d], z);
    z = 1.f / (z + 1e-6f);

    float acc[16] = {};
#pragma unroll
    for (int d = 0; d < 64; d++) {
        float qd = qs[row][d];
#pragma unroll
        for (int m = 0; m < 16; m++)
            acc[m] = fmaf(qd, kvs[d][mo + m], acc[m]);
    }

    float* Ob = O + (size_t)(b * SSZ + s0 + row) * DM + h * DHD + mo;
#pragma unroll
    for (int m = 0; m < 16; m++) acc[m] *= z;
#pragma unroll
    for (int q4 = 0; q4 < 4; q4++)
        *(float4*)(Ob + q4 * 4) = *(float4*)&acc[q4 * 4];
}

// ---------------------------------------------------------------------------
// out = LayerNorm(X (+ Y)) * w + b  over last dim (1024). One block per row.
// ---------------------------------------------------------------------------
__global__ void __launch_bounds__(256) ln_kernel(
    const float* X, const float* Yr, const float* __restrict__ w,
    const float* __restrict__ bb, float* out, int has_res)
{
    __shared__ float ss[8], ssq[8];
    __shared__ float sm, sr;

    const int row = blockIdx.x;
    const int tid = threadIdx.x;
    const int c = tid * 4;

    float4 xv = *(const float4*)(X + (size_t)row * DM + c);
    float v0 = xv.x, v1 = xv.y, v2 = xv.z, v3 = xv.w;
    if (has_res) {
        float4 yv = *(const float4*)(Yr + (size_t)row * DM + c);
        v0 += yv.x; v1 += yv.y; v2 += yv.z; v3 += yv.w;
    }

    float s  = v0 + v1 + v2 + v3;
    float sq = v0 * v0 + v1 * v1 + v2 * v2 + v3 * v3;
#pragma unroll
    for (int off = 16; off; off >>= 1) {
        s  += __shfl_xor_sync(0xffffffffu, s,  off);
        sq += __shfl_xor_sync(0xffffffffu, sq, off);
    }
    const int wid = tid >> 5, lane = tid & 31;
    if (lane == 0) { ss[wid] = s; ssq[wid] = sq; }
    __syncthreads();
    if (tid == 0) {
        float t = 0.f, tq = 0.f;
#pragma unroll
        for (int i = 0; i < 8; i++) { t += ss[i]; tq += ssq[i]; }
        float mean = t * (1.f / DM);
        float var  = tq * (1.f / DM) - mean * mean;
        sm = mean;
        sr = rsqrtf(var + 1e-5f);
    }
    __syncthreads();
    const float mean = sm, rstd = sr;

    float4 wv = *(const float4*)(w + c);
    float4 bv = *(const float4*)(bb + c);
    float4 ov;
    ov.x = (v0 - mean) * rstd * wv.x + bv.x;
    ov.y = (v1 - mean) * rstd * wv.y + bv.y;
    ov.z = (v2 - mean) * rstd * wv.z + bv.z;
    ov.w = (v3 - mean) * rstd * wv.w + bv.w;
    *(float4*)(out + (size_t)row * DM + c) = ov;
}

// ---------------------------------------------------------------------------
// Orchestration
// ---------------------------------------------------------------------------
extern "C" void kernel_launch(void* const* d_in, const int* in_sizes, int n_in,
                              void* d_out, int out_size)
{
    const float* x    = (const float*)d_in[0];
    const float* Wq   = (const float*)d_in[1];
    const float* bq   = (const float*)d_in[2];
    const float* Wk   = (const float*)d_in[3];
    const float* bk   = (const float*)d_in[4];
    const float* Wv   = (const float*)d_in[5];
    const float* bv   = (const float*)d_in[6];
    const float* Wo   = (const float*)d_in[7];
    const float* bo   = (const float*)d_in[8];
    const float* ln1w = (const float*)d_in[9];
    const float* ln1b = (const float*)d_in[10];
    const float* W1   = (const float*)d_in[11];
    const float* b1   = (const float*)d_in[12];
    const float* W2   = (const float*)d_in[13];
    const float* b2   = (const float*)d_in[14];
    const float* ln2w = (const float*)d_in[15];
    const float* ln2b = (const float*)d_in[16];
    const float* lnfw = (const float*)d_in[17];
    const float* lnfb = (const float*)d_in[18];

    float *X, *Q, *Kb, *Vb, *T, *F, *KV, *KS;
    cudaGetSymbolAddress((void**)&X,  g_X);
    cudaGetSymbolAddress((void**)&Q,  g_Q);
    cudaGetSymbolAddress((void**)&Kb, g_K);
    cudaGetSymbolAddress((void**)&Vb, g_V);
    cudaGetSymbolAddress((void**)&T,  g_T);
    cudaGetSymbolAddress((void**)&F,  g_F);
    cudaGetSymbolAddress((void**)&KV, g_KV);
    cudaGetSymbolAddress((void**)&KS, g_KS);

    copy_kernel<<<(MS * DM) / 1024, 256>>>(x, X);

    const dim3 gD(DM / 128, MS / 128);      // (8, 64)  for N=1024
    const dim3 gF1(DFF_ / 128, MS / 128);   // (32, 64) for N=4096

    for (int l = 0; l < LNUM; l++) {
        const float* wq = Wq + (size_t)l * DM * DM;
        const float* wk = Wk + (size_t)l * DM * DM;
        const float* wv = Wv + (size_t)l * DM * DM;
        const float* wo = Wo + (size_t)l * DM * DM;
        const float* w1 = W1 + (size_t)l * DM * DFF_;
        const float* w2 = W2 + (size_t)l * DFF_ * DM;
        const float* bqL = bq + (size_t)l * DM;
        const float* bkL = bk + (size_t)l * DM;
        const float* bvL = bv + (size_t)l * DM;
        const float* boL = bo + (size_t)l * DM;
        const float* b1L = b1 + (size_t)l * DFF_;
        const float* b2L = b2 + (size_t)l * DM;
        const float* l1w = ln1w + (size_t)l * DM;
        const float* l1b = ln1b + (size_t)l * DM;
        const float* l2w = ln2w + (size_t)l * DM;
        const float* l2b = ln2b + (size_t)l * DM;

        // Q = phi(X Wq + bq), K = phi(X Wk + bk), V = X Wv + bv
        gemm_kernel<1><<<gD, 256>>>(X, wq, bqL, Q,  MS, DM, DM);
        gemm_kernel<1><<<gD, 256>>>(X, wk, bkL, Kb, MS, DM, DM);
        gemm_kernel<0><<<gD, 256>>>(X, wv, bvL, Vb, MS, DM, DM);

        // kv, ksum
        kv_reduce_kernel<<<BSZ * HH, 256>>>(Kb, Vb, KV, KS);

        // attn out (pre-projection) -> T
        attn_out_kernel<<<dim3(BSZ * HH, SSZ / 64), 256>>>(Q, KV, KS, T);

        // projection -> Vb (free now), then X = LN1(X + Vb)
        gemm_kernel<0><<<gD, 256>>>(T, wo, boL, Vb, MS, DM, DM);
        ln_kernel<<<MS, 256>>>(X, Vb, l1w, l1b, X, 1);

        // FFN: F = relu(X W1 + b1); T = F W2 + b2; X = LN2(X + T)
        gemm_kernel<2><<<gF1, 256>>>(X, w1, b1L, F, MS, DFF_, DM);
        gemm_kernel<0><<<gD, 256>>>(F, w2, b2L, T, MS, DM, DFF_);
        ln_kernel<<<MS, 256>>>(X, T, l2w, l2b, X, 1);
    }

    // final LayerNorm -> d_out
    ln_kernel<<<MS, 256>>>(X, X, lnfw, lnfb, (float*)d_out, 0);
}

// round 6
// speedup vs baseline: 1.0005x; 1.0005x over previous
#include <cuda_runtime.h>
#include <math.h>

// Problem constants
#define BSZ   4
#define SSZ   2048
#define DM    1024
#define HH    16
#define DHD   64
#define DFF_  4096
#define LNUM  6
#define MS    (BSZ*SSZ)   // 8192 rows

// ---------------------------------------------------------------------------
// Scratch (device globals — no allocation allowed)
// ---------------------------------------------------------------------------
__device__ float g_X[MS*DM];     // running activations
__device__ float g_Q[MS*DM];
__device__ float g_K[MS*DM];
__device__ float g_V[MS*DM];
__device__ float g_T[MS*DM];     // attn output / ffn tmp
__device__ float g_F[(size_t)MS*DFF_];   // ffn hidden
__device__ float g_KV[BSZ*HH*DHD*DHD];
__device__ float g_KS[BSZ*HH*DHD];

// ---------------------------------------------------------------------------
// copy x -> g_X
// ---------------------------------------------------------------------------
__global__ void __launch_bounds__(256) copy_kernel(const float* __restrict__ src,
                                                   float* __restrict__ dst)
{
    size_t i = ((size_t)blockIdx.x * 256 + threadIdx.x) * 4;
    *(float4*)(dst + i) = *(const float4*)(src + i);
}

// ---------------------------------------------------------------------------
// Tiled SGEMM: C[M,N] = act(A[M,K] @ W[K,N] + bias[N])
// ACT: 0 = none, 1 = elu+1 (phi), 2 = relu
// BM=BN=128, BK=16, 256 threads, 8x8 per-thread microtile.
// ---------------------------------------------------------------------------
template<int ACT>
__global__ void __launch_bounds__(256) gemm_kernel(
    const float* __restrict__ A, const float* __restrict__ W,
    const float* __restrict__ bias, float* __restrict__ C,
    int M, int N, int K)
{
    __shared__ float As[16][128];   // A^T tile: As[k][m]
    __shared__ float Bs[16][128];   // Bs[k][n]

    const int tid = threadIdx.x;
    const int bx = blockIdx.x;      // N tile
    const int by = blockIdx.y;      // M tile

    const float* Ab = A + (size_t)by * 128 * K;
    const float* Wb = W + (size_t)bx * 128;

    const int ty = tid >> 4, tx = tid & 15;
    const int row0 = ty * 8, col0 = tx * 8;

    float acc[8][8];
#pragma unroll
    for (int i = 0; i < 8; i++)
#pragma unroll
        for (int j = 0; j < 8; j++) acc[i][j] = 0.f;

    for (int k0 = 0; k0 < K; k0 += 16) {
#pragma unroll
        for (int j = 0; j < 2; j++) {
            int idx = tid + j * 256;          // 0..511
            // A tile: 128 rows x 16 cols  = 512 float4 (4 per row)
            int r  = idx >> 2;
            int c4 = (idx & 3) * 4;
            float4 va = *(const float4*)(Ab + (size_t)r * K + k0 + c4);
            As[c4 + 0][r] = va.x;
            As[c4 + 1][r] = va.y;
            As[c4 + 2][r] = va.z;
            As[c4 + 3][r] = va.w;
            // B tile: 16 rows x 128 cols = 512 float4 (32 per row)
            int kr = idx >> 5;
            int n4 = (idx & 31) * 4;
            float4 vb = *(const float4*)(Wb + (size_t)(k0 + kr) * N + n4);
            *(float4*)&Bs[kr][n4] = vb;
        }
        __syncthreads();

#pragma unroll
        for (int kk = 0; kk < 16; kk++) {
            float a[8], bb[8];
            *(float4*)&a[0]  = *(const float4*)&As[kk][row0];
            *(float4*)&a[4]  = *(const float4*)&As[kk][row0 + 4];
            *(float4*)&bb[0] = *(const float4*)&Bs[kk][col0];
            *(float4*)&bb[4] = *(const float4*)&Bs[kk][col0 + 4];
#pragma unroll
            for (int i = 0; i < 8; i++)
#pragma unroll
                for (int j = 0; j < 8; j++)
                    acc[i][j] = fmaf(a[i], bb[j], acc[i][j]);
        }
        __syncthreads();
    }

    float bj[8];
#pragma unroll
    for (int j = 0; j < 8; j++) bj[j] = bias[bx * 128 + col0 + j];

    float* Cb = C + (size_t)(by * 128) * N + bx * 128;
#pragma unroll
    for (int i = 0; i < 8; i++) {
        float o[8];
#pragma unroll
        for (int j = 0; j < 8; j++) {
            float v = acc[i][j] + bj[j];
            if (ACT == 1) v = (v > 0.f) ? (v + 1.f) : __expf(v);  // elu(v)+1
            if (ACT == 2) v = fmaxf(v, 0.f);
            o[j] = v;
        }
        *(float4*)(Cb + (size_t)(row0 + i) * N + col0)     = *(float4*)&o[0];
        *(float4*)(Cb + (size_t)(row0 + i) * N + col0 + 4) = *(float4*)&o[4];
    }
}

// ---------------------------------------------------------------------------
// kv[b,h,d,m] = sum_s k[b,s,h,d] * v[b,s,h,m];  ksum[b,h,d] = sum_s k[b,s,h,d]
// grid = B*H blocks, 256 threads; each thread owns a 4x4 tile of the 64x64 kv.
// ---------------------------------------------------------------------------
__global__ void __launch_bounds__(256) kv_reduce_kernel(
    const float* __restrict__ Kx, const float* __restrict__ Vx,
    float* __restrict__ KVo, float* __restrict__ KSo)
{
    const int bh = blockIdx.x;
    const int b = bh >> 4, h = bh & 15;
    const float* Kb = Kx + (size_t)b * SSZ * DM + h * DHD;
    const float* Vb = Vx + (size_t)b * SSZ * DM + h * DHD;

    __shared__ float ks[32][64];
    __shared__ float vs[32][64];

    const int tid = threadIdx.x;
    const int ty = tid >> 4, tx = tid & 15;

    float acc[4][4] = {};
    float ksum = 0.f;

    for (int s0 = 0; s0 < SSZ; s0 += 32) {
#pragma unroll
        for (int j = 0; j < 2; j++) {
            int idx = tid + j * 256;
            int r = idx >> 4, c4 = (idx & 15) * 4;
            *(float4*)&ks[r][c4] = *(const float4*)(Kb + (size_t)(s0 + r) * DM + c4);
            *(float4*)&vs[r][c4] = *(const float4*)(Vb + (size_t)(s0 + r) * DM + c4);
        }
        __syncthreads();

#pragma unroll 8
        for (int s = 0; s < 32; s++) {
            float a[4], bv[4];
#pragma unroll
            for (int i = 0; i < 4; i++) a[i] = ks[s][ty * 4 + i];
#pragma unroll
            for (int j = 0; j < 4; j++) bv[j] = vs[s][tx * 4 + j];
#pragma unroll
            for (int i = 0; i < 4; i++)
#pragma unroll
                for (int j = 0; j < 4; j++)
                    acc[i][j] = fmaf(a[i], bv[j], acc[i][j]);
        }
        if (tid < 64) {
#pragma unroll 8
            for (int s = 0; s < 32; s++) ksum += ks[s][tid];
        }
        __syncthreads();
    }

    float* KVb = KVo + (size_t)bh * DHD * DHD;
#pragma unroll
    for (int i = 0; i < 4; i++)
#pragma unroll
        for (int j = 0; j < 4; j++)
            KVb[(ty * 4 + i) * DHD + tx * 4 + j] = acc[i][j];
    if (tid < 64) KSo[bh * DHD + tid] = ksum;
}

// ---------------------------------------------------------------------------
// o[b,s,h,m] = z * sum_d q[b,s,h,d] * kv[b,h,d,m],  z = 1/(q . ksum + 1e-6)
// grid = (B*H, S/64), 256 threads; 64 q-rows per block, 16 out cols per thread.
// ---------------------------------------------------------------------------
__global__ void __launch_bounds__(256) attn_out_kernel(
    const float* __restrict__ Qx, const float* __restrict__ KVi,
    const float* __restrict__ KSi, float* __restrict__ O)
{
    const int bh = blockIdx.x;
    const int b = bh >> 4, h = bh & 15;
    const int s0 = blockIdx.y * 64;

    __shared__ float qs[64][64];
    __shared__ float kvs[64][64];
    __shared__ float kss[64];

    const int tid = threadIdx.x;
    const float* Qb  = Qx + (size_t)(b * SSZ + s0) * DM + h * DHD;
    const float* KVb = KVi + (size_t)bh * DHD * DHD;

#pragma unroll
    for (int j = 0; j < 4; j++) {
        int idx = tid + j * 256;
        int r = idx >> 4, c4 = (idx & 15) * 4;
        *(float4*)&qs[r][c4]  = *(const float4*)(Qb + (size_t)r * DM + c4);
        *(float4*)&kvs[r][c4] = *(const float4*)(KVb + r * DHD + c4);
    }
    if (tid < 64) kss[tid] = KSi[bh * DHD + tid];
    __syncthreads();

    const int row = tid >> 2;
    const int mo  = (tid & 3) * 16;

    float z = 0.f;
#pragma unroll
    for (int d = 0; d < 64; d++) z = fmaf(qs[row][d], kss[d], z);
    z = 1.f / (z + 1e-6f);

    float acc[16] = {};
#pragma unroll
    for (int d = 0; d < 64; d++) {
        float qd = qs[row][d];
#pragma unroll
        for (int m = 0; m < 16; m++)
            acc[m] = fmaf(qd, kvs[d][mo + m], acc[m]);
    }

    float* Ob = O + (size_t)(b * SSZ + s0 + row) * DM + h * DHD + mo;
#pragma unroll
    for (int m = 0; m < 16; m++) acc[m] *= z;
#pragma unroll
    for (int q4 = 0; q4 < 4; q4++)
        *(float4*)(Ob + q4 * 4) = *(float4*)&acc[q4 * 4];
}

// ---------------------------------------------------------------------------
// out = LayerNorm(X (+ Y)) * w + b  over last dim (1024). One block per row.
// ---------------------------------------------------------------------------
__global__ void __launch_bounds__(256) ln_kernel(
    const float* X, const float* Yr, const float* __restrict__ w,
    const float* __restrict__ bb, float* out, int has_res)
{
    __shared__ float ss[8], ssq[8];
    __shared__ float sm, sr;

    const int row = blockIdx.x;
    const int tid = threadIdx.x;
    const int c = tid * 4;

    float4 xv = *(const float4*)(X + (size_t)row * DM + c);
    float v0 = xv.x, v1 = xv.y, v2 = xv.z, v3 = xv.w;
    if (has_res) {
        float4 yv = *(const float4*)(Yr + (size_t)row * DM + c);
        v0 += yv.x; v1 += yv.y; v2 += yv.z; v3 += yv.w;
    }

    float s  = v0 + v1 + v2 + v3;
    float sq = v0 * v0 + v1 * v1 + v2 * v2 + v3 * v3;
#pragma unroll
    for (int off = 16; off; off >>= 1) {
        s  += __shfl_xor_sync(0xffffffffu, s,  off);
        sq += __shfl_xor_sync(0xffffffffu, sq, off);
    }
    const int wid = tid >> 5, lane = tid & 31;
    if (lane == 0) { ss[wid] = s; ssq[wid] = sq; }
    __syncthreads();
    if (tid == 0) {
        float t = 0.f, tq = 0.f;
#pragma unroll
        for (int i = 0; i < 8; i++) { t += ss[i]; tq += ssq[i]; }
        float mean = t * (1.f / DM);
        float var  = tq * (1.f / DM) - mean * mean;
        sm = mean;
        sr = rsqrtf(var + 1e-5f);
    }
    __syncthreads();
    const float mean = sm, rstd = sr;

    float4 wv = *(const float4*)(w + c);
    float4 bv = *(const float4*)(bb + c);
    float4 ov;
    ov.x = (v0 - mean) * rstd * wv.x + bv.x;
    ov.y = (v1 - mean) * rstd * wv.y + bv.y;
    ov.z = (v2 - mean) * rstd * wv.z + bv.z;
    ov.w = (v3 - mean) * rstd * wv.w + bv.w;
    *(float4*)(out + (size_t)row * DM + c) = ov;
}

// ---------------------------------------------------------------------------
// Orchestration
// ---------------------------------------------------------------------------
extern "C" void kernel_launch(void* const* d_in, const int* in_sizes, int n_in,
                              void* d_out, int out_size)
{
    const float* x    = (const float*)d_in[0];
    const float* Wq   = (const float*)d_in[1];
    const float* bq   = (const float*)d_in[2];
    const float* Wk   = (const float*)d_in[3];
    const float* bk   = (const float*)d_in[4];
    const float* Wv   = (const float*)d_in[5];
    const float* bv   = (const float*)d_in[6];
    const float* Wo   = (const float*)d_in[7];
    const float* bo   = (const float*)d_in[8];
    const float* ln1w = (const float*)d_in[9];
    const float* ln1b = (const float*)d_in[10];
    const float* W1   = (const float*)d_in[11];
    const float* b1   = (const float*)d_in[12];
    const float* W2   = (const float*)d_in[13];
    const float* b2   = (const float*)d_in[14];
    const float* ln2w = (const float*)d_in[15];
    const float* ln2b = (const float*)d_in[16];
    const float* lnfw = (const float*)d_in[17];
    const float* lnfb = (const float*)d_in[18];

    float *X, *Q, *Kb, *Vb, *T, *F, *KV, *KS;
    cudaGetSymbolAddress((void**)&X,  g_X);
    cudaGetSymbolAddress((void**)&Q,  g_Q);
    cudaGetSymbolAddress((void**)&Kb, g_K);
    cudaGetSymbolAddress((void**)&Vb, g_V);
    cudaGetSymbolAddress((void**)&T,  g_T);
    cudaGetSymbolAddress((void**)&F,  g_F);
    cudaGetSymbolAddress((void**)&KV, g_KV);
    cudaGetSymbolAddress((void**)&KS, g_KS);

    copy_kernel<<<(MS * DM) / 1024, 256>>>(x, X);

    const dim3 gD(DM / 128, MS / 128);      // (8, 64)  for N=1024
    const dim3 gF1(DFF_ / 128, MS / 128);   // (32, 64) for N=4096

    for (int l = 0; l < LNUM; l++) {
        const float* wq = Wq + (size_t)l * DM * DM;
        const float* wk = Wk + (size_t)l * DM * DM;
        const float* wv = Wv + (size_t)l * DM * DM;
        const float* wo = Wo + (size_t)l * DM * DM;
        const float* w1 = W1 + (size_t)l * DM * DFF_;
        const float* w2 = W2 + (size_t)l * DFF_ * DM;
        const float* bqL = bq + (size_t)l * DM;
        const float* bkL = bk + (size_t)l * DM;
        const float* bvL = bv + (size_t)l * DM;
        const float* boL = bo + (size_t)l * DM;
        const float* b1L = b1 + (size_t)l * DFF_;
        const float* b2L = b2 + (size_t)l * DM;
        const float* l1w = ln1w + (size_t)l * DM;
        const float* l1b = ln1b + (size_t)l * DM;
        const float* l2w = ln2w + (size_t)l * DM;
        const float* l2b = ln2b + (size_t)l * DM;

        // Q = phi(X Wq + bq), K = phi(X Wk + bk), V = X Wv + bv
        gemm_kernel<1><<<gD, 256>>>(X, wq, bqL, Q,  MS, DM, DM);
        gemm_kernel<1><<<gD, 256>>>(X, wk, bkL, Kb, MS, DM, DM);
        gemm_kernel<0><<<gD, 256>>>(X, wv, bvL, Vb, MS, DM, DM);

        // kv, ksum
        kv_reduce_kernel<<<BSZ * HH, 256>>>(Kb, Vb, KV, KS);

        // attn out (pre-projection) -> T
        attn_out_kernel<<<dim3(BSZ * HH, SSZ / 64), 256>>>(Q, KV, KS, T);

        // projection -> Vb (free now), then X = LN1(X + Vb)
        gemm_kernel<0><<<gD, 256>>>(T, wo, boL, Vb, MS, DM, DM);
        ln_kernel<<<MS, 256>>>(X, Vb, l1w, l1b, X, 1);

        // FFN: F = relu(X W1 + b1); T = F W2 + b2; X = LN2(X + T)
        gemm_kernel<2><<<gF1, 256>>>(X, w1, b1L, F, MS, DFF_, DM);
        gemm_kernel<0><<<gD, 256>>>(F, w2, b2L, T, MS, DM, DFF_);
        ln_kernel<<<MS, 256>>>(X, T, l2w, l2b, X, 1);
    }

    // final LayerNorm -> d_out
    ln_kernel<<<MS, 256>>>(X, X, lnfw, lnfb, (float*)d_out, 0);
}